// round 15
// baseline (speedup 1.0000x reference)
#include <cuda_runtime.h>
#include <cuda_fp16.h>
#include <cstdint>

#define HID 256
#define NB 4096
#define NTOT 131072

// Scratch (allocation-free rule: __device__ globals)
__device__ float  g_Q[(size_t)NB * HID];
__device__ __half g_K[(size_t)NTOT * HID];
__device__ __half g_V[(size_t)NTOT * HID];
__device__ __half g_O[(size_t)NB * HID];
__device__ __half g_Wk16[HID * HID];
__device__ __half g_Wv16[HID * HID];
__device__ __half g_Wq16[HID * HID];
__device__ __half g_Wf16[HID * HID];
__device__ int    g_idx[NTOT];
__device__ unsigned char g_flag[NTOT];
__device__ int    g_count;

// ======================= helpers =======================
__device__ __forceinline__ void mma_f16(float* d, const uint32_t* a, const uint32_t* b) {
    asm volatile(
        "mma.sync.aligned.m16n8k16.row.col.f32.f16.f16.f32 "
        "{%0,%1,%2,%3},{%4,%5,%6,%7},{%8,%9},{%0,%1,%2,%3};"
        : "+f"(d[0]), "+f"(d[1]), "+f"(d[2]), "+f"(d[3])
        : "r"(a[0]), "r"(a[1]), "r"(a[2]), "r"(a[3]), "r"(b[0]), "r"(b[1]));
}
__device__ __forceinline__ uint32_t h2u(float lo, float hi) {
    __half2 h = __floats2half2_rn(lo, hi);
    return *(uint32_t*)&h;
}
__device__ __forceinline__ uint32_t smem_u32(const void* p) {
    return (uint32_t)__cvta_generic_to_shared(p);
}
__device__ __forceinline__ void ldsm_x4(uint32_t& r0, uint32_t& r1, uint32_t& r2, uint32_t& r3,
                                        uint32_t addr) {
    asm volatile("ldmatrix.sync.aligned.m8n8.x4.shared.b16 {%0,%1,%2,%3}, [%4];"
                 : "=r"(r0), "=r"(r1), "=r"(r2), "=r"(r3) : "r"(addr));
}
__device__ __forceinline__ void cpa16(uint32_t dst, const void* src) {
    asm volatile("cp.async.ca.shared.global [%0], [%1], 16;" :: "r"(dst), "l"(src));
}
__device__ __forceinline__ void cpa_commit() {
    asm volatile("cp.async.commit_group;" ::: "memory");
}
__device__ __forceinline__ void cpa_wait2() {
    asm volatile("cp.async.wait_group 2;" ::: "memory");
}
__device__ __forceinline__ void cpa_wait0() {
    asm volatile("cp.async.wait_all;" ::: "memory");
}

#define AST2 132
#define BST2 20
#define BBUF (128 * BST2)
#define KV_SMEM ((128 * AST2 + 4 * BBUF) * 4)
#define FIN_SMEM ((32 * AST2 + 4 * BBUF) * 4)

// ======== prep: zero flags/idx/count + weights fp32->fp16 (fused) ========
__global__ void __launch_bounds__(256) prep(
    const float* __restrict__ Wk, const float* __restrict__ Wv,
    const float* __restrict__ Wq, const float* __restrict__ Wf)
{
    const int i = blockIdx.x * 256 + threadIdx.x;    // grid 512 -> 131072
    g_idx[i] = 0;
    if (i < NTOT / 4) ((int*)g_flag)[i] = 0;
    if (i == 0) g_count = 0;
    if (i < HID * HID) {
        g_Wk16[i] = __float2half_rn(Wk[i]);
        g_Wv16[i] = __float2half_rn(Wv[i]);
        g_Wq16[i] = __float2half_rn(Wq[i]);
        g_Wf16[i] = __float2half_rn(Wf[i]);
    }
}

__global__ void __launch_bounds__(256) mark(const int* __restrict__ st,
                                            const int* __restrict__ en) {
    const int w = (blockIdx.x * 256 + threadIdx.x) >> 5;   // grid 128 -> 1024 warps
    const int lane = threadIdx.x & 31;
#pragma unroll
    for (int q = 0; q < 4; q++) {
        const int s = w * 4 + q;
        const int a = st[s], b = en[s];
        for (int r = a + lane; r < b; r += 32) g_flag[r] = 1;
    }
}

__global__ void __launch_bounds__(256) compact() {
    const int i = blockIdx.x * 256 + threadIdx.x;
    const int lane = threadIdx.x & 31;
    const int f = g_flag[i];
    const unsigned mask = __ballot_sync(0xffffffffu, f);
    int base = 0;
    if (lane == 0 && mask) base = atomicAdd(&g_count, __popc(mask));
    base = __shfl_sync(0xffffffffu, base, 0);
    if (f) g_idx[base + __popc(mask & ((1u << lane) - 1u))] = i;
}

// issue one B chunk (128 n-rows x 32 k, fp16) via cp.async into ring slot
__device__ __forceinline__ void issue_b(const __half* W16, int nh, int kc,
                                        uint32_t bufb32, int tid) {
#pragma unroll
    for (int r = 0; r < 2; r++) {
        const int task = tid + r * 256;
        const int n = task >> 2;
        const int s = task & 3;
        cpa16(bufb32 + (uint32_t)((n * BST2 + s * 4) * 4),
              W16 + (size_t)(nh * 128 + n) * HID + kc * 32 + s * 8);
    }
}

// ============ fused K+V+Q projections: gather-GEMM over covered rows ============
__global__ void __launch_bounds__(256, 2)
kvq_mma(const float* __restrict__ soc, const float* __restrict__ enc,
        const float* __restrict__ bk, const float* __restrict__ bv,
        const float* __restrict__ bq,
        __half* __restrict__ Kout, __half* __restrict__ Vout,
        float* __restrict__ Qout)
{
    extern __shared__ uint32_t sm32[];
    uint32_t* As = sm32;
    const uint32_t Abase = smem_u32(As);
    const uint32_t Bbase = Abase + 128 * AST2 * 4;

    const int tid = threadIdx.x;
    const int lane = tid & 31;
    const int wid = tid >> 5;
    const int wm = wid & 1;
    const int wn = wid >> 1;
    const int bm = blockIdx.x;
    const bool isQ = (bm >= NTOT / 128);
    const int rowblk = isQ ? (bm - NTOT / 128) : bm;
    const int ntc_total = isQ ? 16 : 32;
    const int gbase = rowblk * 128;

    if (!isQ && gbase >= g_count) return;

    const int arow = wm * 64 + (lane & 15);
    const int acol = (lane >> 4) << 2;
    const int brow = wn * 32 + ((lane >> 4) << 3) + (lane & 7);
    const int bcol = ((lane >> 3) & 1) << 2;

    const __half* WK16 = isQ ? g_Wq16 : g_Wk16;
    const __half* WV16 = isQ ? g_Wq16 : g_Wv16;
    issue_b(WK16, 0, 0, Bbase, tid);
    cpa_commit();
    issue_b(WK16, 0, 1, Bbase + BBUF * 4, tid);
    cpa_commit();

    // ---- stage A tile 128x256 -> fp16 (gathered rows for KV mode) ----
#pragma unroll
    for (int i = 0; i < 32; i++) {
        int idx = i * 256 + tid;
        int r = idx >> 6, c4 = (idx & 63) << 2;
        const size_t grow = isQ ? (size_t)(gbase + r) : (size_t)g_idx[gbase + r];
        const float* src = (isQ ? enc : soc) + grow * HID + c4;
        float4 v = *(const float4*)src;
        uint2 h;
        h.x = h2u(v.x, v.y);
        h.y = h2u(v.z, v.w);
        *(uint2*)&As[r * AST2 + (c4 >> 1)] = h;
    }
    __syncthreads();

    float acc[4][4][4];
#pragma unroll
    for (int i = 0; i < 4; i++)
#pragma unroll
        for (int j = 0; j < 4; j++)
#pragma unroll
            for (int t = 0; t < 4; t++) acc[i][j][t] = 0.0f;

    for (int tc = 0; tc < ntc_total; tc++) {
        const int p = tc >> 3;
        const int kc = tc & 7;

        uint32_t a0[4][4];
        {
            const int kb = kc * 16;
#pragma unroll
            for (int i = 0; i < 4; i++)
                ldsm_x4(a0[i][0], a0[i][1], a0[i][2], a0[i][3],
                        Abase + (uint32_t)(((arow + i * 16) * AST2 + kb + acol) * 4));
        }

        if (tc + 2 < ntc_total) {
            const int ntc = tc + 2;
            const int np = ntc >> 3, nkc = ntc & 7;
            const __half* W = (np < 2) ? WK16 : WV16;
            issue_b(W, np & 1, nkc, Bbase + (uint32_t)(((ntc) & 3) * BBUF * 4), tid);
        }
        cpa_commit();
        cpa_wait2();
        __syncthreads();

        const uint32_t Bb32 = Bbase + (uint32_t)((tc & 3) * BBUF * 4);

        // ks = 0
        {
            uint32_t b[4][2];
            ldsm_x4(b[0][0], b[0][1], b[1][0], b[1][1],
                    Bb32 + (uint32_t)((brow * BST2 + bcol) * 4));
            ldsm_x4(b[2][0], b[2][1], b[3][0], b[3][1],
                    Bb32 + (uint32_t)(((brow + 16) * BST2 + bcol) * 4));
#pragma unroll
            for (int i = 0; i < 4; i++)
#pragma unroll
                for (int j = 0; j < 4; j++) mma_f16(acc[i][j], a0[i], b[j]);
        }
        // ks = 1
        {
            const int kb = kc * 16 + 8;
            uint32_t a[4][4];
#pragma unroll
            for (int i = 0; i < 4; i++)
                ldsm_x4(a[i][0], a[i][1], a[i][2], a[i][3],
                        Abase + (uint32_t)(((arow + i * 16) * AST2 + kb + acol) * 4));
            uint32_t b[4][2];
            const int bk0 = 8 + bcol;
            ldsm_x4(b[0][0], b[0][1], b[1][0], b[1][1],
                    Bb32 + (uint32_t)((brow * BST2 + bk0) * 4));
            ldsm_x4(b[2][0], b[2][1], b[3][0], b[3][1],
                    Bb32 + (uint32_t)(((brow + 16) * BST2 + bk0) * 4));
#pragma unroll
            for (int i = 0; i < 4; i++)
#pragma unroll
                for (int j = 0; j < 4; j++) mma_f16(acc[i][j], a[i], b[j]);
        }

        if (kc == 7) {
            const int nh = p & 1;
            const int colw = nh * 128 + wn * 32 + (lane & 3) * 2;
            const int lrow = wm * 64 + (lane >> 2);
            if (isQ) {
#pragma unroll
                for (int j = 0; j < 4; j++) {
                    const float2 bb = *(const float2*)&bq[colw + j * 8];
#pragma unroll
                    for (int i = 0; i < 4; i++) {
                        const size_t r0 = (size_t)gbase + lrow + i * 16;
                        float2 o0, o1;
                        o0.x = fmaxf(acc[i][j][0] + bb.x, 0.0f) * 0.0625f;
                        o0.y = fmaxf(acc[i][j][1] + bb.y, 0.0f) * 0.0625f;
                        o1.x = fmaxf(acc[i][j][2] + bb.x, 0.0f) * 0.0625f;
                        o1.y = fmaxf(acc[i][j][3] + bb.y, 0.0f) * 0.0625f;
                        *(float2*)&Qout[r0 * HID + colw + j * 8] = o0;
                        *(float2*)&Qout[(r0 + 8) * HID + colw + j * 8] = o1;
#pragma unroll
                        for (int t = 0; t < 4; t++) acc[i][j][t] = 0.0f;
                    }
                }
            } else {
                const float* bias = (p < 2) ? bk : bv;
                __half* Cout = (p < 2) ? Kout : Vout;
#pragma unroll
                for (int i = 0; i < 4; i++) {
                    const size_t r0 = (size_t)g_idx[gbase + lrow + i * 16];
                    const size_t r1 = (size_t)g_idx[gbase + lrow + i * 16 + 8];
#pragma unroll
                    for (int j = 0; j < 4; j++) {
                        const float2 bb = *(const float2*)&bias[colw + j * 8];
                        uint32_t u0 = h2u(fmaxf(acc[i][j][0] + bb.x, 0.0f),
                                          fmaxf(acc[i][j][1] + bb.y, 0.0f));
                        uint32_t u1 = h2u(fmaxf(acc[i][j][2] + bb.x, 0.0f),
                                          fmaxf(acc[i][j][3] + bb.y, 0.0f));
                        *(uint32_t*)&Cout[r0 * HID + colw + j * 8] = u0;
                        *(uint32_t*)&Cout[r1 * HID + colw + j * 8] = u1;
#pragma unroll
                        for (int t = 0; t < 4; t++) acc[i][j][t] = 0.0f;
                    }
                }
            }
        }
    }
}

// ============ final projection: 32-row tiles, 128 CTAs (mma.sync fp16) ============
__global__ void __launch_bounds__(256, 2)
fin_mma(const __half* __restrict__ O, const float* __restrict__ bf,
        float* __restrict__ out)
{
    extern __shared__ uint32_t sm32[];
    uint32_t* As = sm32;
    const uint32_t Abase = smem_u32(As);
    const uint32_t Bbase = Abase + 32 * AST2 * 4;

    const int tid = threadIdx.x;
    const int lane = tid & 31;
    const int wid = tid >> 5;
    const int wm = wid & 1;
    const int wn = wid >> 1;
    const int bm = blockIdx.x;

    const int arow = wm * 16 + (lane & 15);
    const int acol = (lane >> 4) << 2;
    const int brow = wn * 32 + ((lane >> 4) << 3) + (lane & 7);
    const int bcol = ((lane >> 3) & 1) << 2;

    issue_b(g_Wf16, 0, 0, Bbase, tid);
    cpa_commit();
    issue_b(g_Wf16, 0, 1, Bbase + BBUF * 4, tid);
    cpa_commit();

    const __half* Ab = O + (size_t)bm * 32 * HID;
#pragma unroll
    for (int i = 0; i < 4; i++) {
        int idx = i * 256 + tid;
        int r = idx >> 5, c2 = (idx & 31) * 4;
        uint4 v = *(const uint4*)(Ab + (size_t)r * HID + c2 * 2);
        *(uint4*)&As[r * AST2 + c2] = v;
    }
    __syncthreads();

    float acc[4][4];
#pragma unroll
    for (int j = 0; j < 4; j++)
#pragma unroll
        for (int t = 0; t < 4; t++) acc[j][t] = 0.0f;

    for (int tc = 0; tc < 16; tc++) {
        const int p = tc >> 3;
        const int kc = tc & 7;

        uint32_t a0[4];
        ldsm_x4(a0[0], a0[1], a0[2], a0[3],
                Abase + (uint32_t)((arow * AST2 + kc * 16 + acol) * 4));

        if (tc + 2 < 16) {
            const int ntc = tc + 2;
            issue_b(g_Wf16, (ntc >> 3) & 1, ntc & 7,
                    Bbase + (uint32_t)((ntc & 3) * BBUF * 4), tid);
        }
        cpa_commit();
        cpa_wait2();
        __syncthreads();

        const uint32_t Bb32 = Bbase + (uint32_t)((tc & 3) * BBUF * 4);
        {
            uint32_t b[4][2];
            ldsm_x4(b[0][0], b[0][1], b[1][0], b[1][1],
                    Bb32 + (uint32_t)((brow * BST2 + bcol) * 4));
            ldsm_x4(b[2][0], b[2][1], b[3][0], b[3][1],
                    Bb32 + (uint32_t)(((brow + 16) * BST2 + bcol) * 4));
#pragma unroll
            for (int j = 0; j < 4; j++) mma_f16(acc[j], a0, b[j]);
        }
        {
            uint32_t a[4];
            ldsm_x4(a[0], a[1], a[2], a[3],
                    Abase + (uint32_t)((arow * AST2 + kc * 16 + 8 + acol) * 4));
            uint32_t b[4][2];
            const int bk0 = 8 + bcol;
            ldsm_x4(b[0][0], b[0][1], b[1][0], b[1][1],
                    Bb32 + (uint32_t)((brow * BST2 + bk0) * 4));
            ldsm_x4(b[2][0], b[2][1], b[3][0], b[3][1],
                    Bb32 + (uint32_t)(((brow + 16) * BST2 + bk0) * 4));
#pragma unroll
            for (int j = 0; j < 4; j++) mma_f16(acc[j], a, b[j]);
        }

        if (kc == 7) {
            const int nh = p & 1;
            const int colw = nh * 128 + wn * 32 + (lane & 3) * 2;
            const size_t rowb = (size_t)bm * 32 + wm * 16 + (lane >> 2);
#pragma unroll
            for (int j = 0; j < 4; j++) {
                const float2 bb = *(const float2*)&bf[colw + j * 8];
                float2 o0, o1;
                o0.x = acc[j][0] + bb.x;
                o0.y = acc[j][1] + bb.y;
                o1.x = acc[j][2] + bb.x;
                o1.y = acc[j][3] + bb.y;
                *(float2*)&out[rowb * HID + colw + j * 8] = o0;
                *(float2*)&out[(rowb + 8) * HID + colw + j * 8] = o1;
#pragma unroll
                for (int t = 0; t < 4; t++) acc[j][t] = 0.0f;
            }
        }
    }
}

// ===== attention: 1 CTA / sample, 512 threads; V->smem prefetch; split-m AV =====
__global__ __launch_bounds__(512) void attn6(
    const float* __restrict__ Q, const __half* __restrict__ K,
    const __half* __restrict__ V, const int* __restrict__ starts,
    const int* __restrict__ ends, __half* __restrict__ O)
{
    __shared__ __half Vs[64 * HID];    // 32 KB
    __shared__ float qs[256];
    __shared__ float sc[256];
    __shared__ float po[512];          // partial AV sums

    const int tid = threadIdx.x;
    const int lane = tid & 31;
    const int wid = tid >> 5;          // 0..15
    const int b = blockIdx.x;
    const int st = starts[b];
    const int len = ends[b] - st;      // 1..64

    // ---- issue V segment prefetch (512 threads -> <=2 chunks each) ----
    {
        const uint32_t vb = smem_u32(Vs);
        const int nch = len * 32;       // 16B chunks
        for (int c = tid; c < nch; c += 512)
            cpa16(vb + (uint32_t)c * 16, (const char*)(V + (size_t)st * HID) + (size_t)c * 16);
        cpa_commit();
    }

    if (tid < 256) {
        qs[tid] = Q[(size_t)b * HID + tid];
        sc[tid] = -1e30f;
    }
    __syncthreads();

    float4 q0 = *(const float4*)&qs[lane * 8];
    float4 q1 = *(const float4*)&qs[lane * 8 + 4];
    const int head = lane >> 3;

    // scores: 16 warps, warp w -> rows m = w, w+16, w+32, w+48
#pragma unroll
    for (int rr = 0; rr < 4; rr++) {
        const int m = rr * 16 + wid;
        if (m < len) {
            uint4 raw = *(const uint4*)(K + (size_t)(st + m) * HID + lane * 8);
            float2 f0 = __half22float2(*(__half2*)&raw.x);
            float2 f1 = __half22float2(*(__half2*)&raw.y);
            float2 f2 = __half22float2(*(__half2*)&raw.z);
            float2 f3 = __half22float2(*(__half2*)&raw.w);
            float p = q0.x * f0.x + q0.y * f0.y + q0.z * f1.x + q0.w * f1.y
                    + q1.x * f2.x + q1.y * f2.y + q1.z * f3.x + q1.w * f3.y;
            p += __shfl_down_sync(0xffffffffu, p, 4);
            p += __shfl_down_sync(0xffffffffu, p, 2);
            p += __shfl_down_sync(0xffffffffu, p, 1);
            if ((lane & 7) == 0) sc[head * 64 + m] = p;
        }
    }
    __syncthreads();

    // softmax: warp w -> head w (first 4 warps)
    if (tid < 128) {
        const int h = tid >> 5, l = tid & 31;
        float v0 = sc[h * 64 + l];
        float v1 = sc[h * 64 + 32 + l];
        float mx = fmaxf(v0, v1);
#pragma unroll
        for (int off = 16; off > 0; off >>= 1)
            mx = fmaxf(mx, __shfl_xor_sync(0xffffffffu, mx, off));
        float e0 = __expf(v0 - mx);
        float e1 = __expf(v1 - mx);
        float sum = e0 + e1;
#pragma unroll
        for (int off = 16; off > 0; off >>= 1)
            sum += __shfl_xor_sync(0xffffffffu, sum, off);
        float inv = 1.0f / sum;
        sc[h * 64 + l] = e0 * inv;
        sc[h * 64 + 32 + l] = e1 * inv;
    }
    cpa_wait0();
    __syncthreads();

    // AV: group g = tid>>8 handles m in [g ? mid : 0, g ? len : mid)
    {
        const int g = tid >> 8;
        const int col = tid & 255;
        const int h = col >> 6;
        const int mid = len >> 1;
        const int mlo = g ? mid : 0;
        const int mhi = g ? len : mid;
        const __half* vp = Vs + col;
        const float* ap = &sc[h * 64];
        float o = 0.0f;
        int m = mlo;
        for (; m + 4 <= mhi; m += 4) {
            float a0 = ap[m], a1 = ap[m + 1], a2 = ap[m + 2], a3 = ap[m + 3];
            float v0 = __half2float(vp[(m) * HID]);
            float v1 = __half2float(vp[(m + 1) * HID]);
            float v2 = __half2float(vp[(m + 2) * HID]);
            float v3 = __half2float(vp[(m + 3) * HID]);
            o = fmaf(a0, v0, o); o = fmaf(a1, v1, o);
            o = fmaf(a2, v2, o); o = fmaf(a3, v3, o);
        }
        for (; m < mhi; m++) o = fmaf(ap[m], __half2float(vp[m * HID]), o);
        po[tid] = o;
    }
    __syncthreads();
    if (tid < 256)
        O[(size_t)b * HID + tid] = __float2half(po[tid] + po[256 + tid]);
}

// ======================= launch =======================
extern "C" void kernel_launch(void* const* d_in, const int* in_sizes, int n_in,
                              void* d_out, int out_size)
{
    const float* enc = (const float*)d_in[0];
    const float* soc = (const float*)d_in[1];
    const float* Wq = (const float*)d_in[2];
    const float* bq = (const float*)d_in[3];
    const float* Wk = (const float*)d_in[4];
    const float* bk = (const float*)d_in[5];
    const float* Wv = (const float*)d_in[6];
    const float* bv = (const float*)d_in[7];
    const float* Wf = (const float*)d_in[8];
    const float* bf = (const float*)d_in[9];
    const int* st = (const int*)d_in[10];
    const int* en = (const int*)d_in[11];
    float* out = (float*)d_out;

    float* qp;
    __half *kp, *vp, *op;
    cudaGetSymbolAddress((void**)&qp, g_Q);
    cudaGetSymbolAddress((void**)&kp, g_K);
    cudaGetSymbolAddress((void**)&vp, g_V);
    cudaGetSymbolAddress((void**)&op, g_O);

    cudaFuncSetAttribute(kvq_mma, cudaFuncAttributeMaxDynamicSharedMemorySize, KV_SMEM);
    cudaFuncSetAttribute(fin_mma, cudaFuncAttributeMaxDynamicSharedMemorySize, FIN_SMEM);

    // prep: zero coverage state + convert weights (fused)
    prep<<<NTOT / 256, 256>>>(Wk, Wv, Wq, Wf);
    // coverage: mark (plain stores) then compact (ballot scan)
    mark<<<128, 256>>>(st, en);
    compact<<<NTOT / 256, 256>>>();
    // fused K,V,Q projections (KV gathered over covered rows)
    kvq_mma<<<NTOT / 128 + NB / 128, 256, KV_SMEM>>>(
        soc, enc, bk, bv, bq, kp, vp, qp);
    // attention (512 threads, V prefetch, split-m AV)
    attn6<<<NB, 512>>>(qp, kp, vp, st, en, op);
    // final projection via fp16 mma (32-row tiles)
    fin_mma<<<NB / 32, 256, FIN_SMEM>>>(op, bf, out);
}

// round 16
// speedup vs baseline: 1.0253x; 1.0253x over previous
#include <cuda_runtime.h>
#include <cuda_fp16.h>
#include <cstdint>

#define HID 256
#define NB 4096
#define NTOT 131072

// Scratch (allocation-free rule: __device__ globals)
__device__ __half g_Q[(size_t)NB * HID];
__device__ __half g_K[(size_t)NTOT * HID];
__device__ __half g_V[(size_t)NTOT * HID];
__device__ __half g_O[(size_t)NB * HID];
__device__ __half g_Wk16[HID * HID];
__device__ __half g_Wv16[HID * HID];
__device__ __half g_Wq16[HID * HID];
__device__ __half g_Wf16[HID * HID];
__device__ int    g_idx[NTOT];
__device__ unsigned char g_flag[NTOT];
__device__ int    g_count;

// ======================= helpers =======================
__device__ __forceinline__ void mma_f16(float* d, const uint32_t* a, const uint32_t* b) {
    asm volatile(
        "mma.sync.aligned.m16n8k16.row.col.f32.f16.f16.f32 "
        "{%0,%1,%2,%3},{%4,%5,%6,%7},{%8,%9},{%0,%1,%2,%3};"
        : "+f"(d[0]), "+f"(d[1]), "+f"(d[2]), "+f"(d[3])
        : "r"(a[0]), "r"(a[1]), "r"(a[2]), "r"(a[3]), "r"(b[0]), "r"(b[1]));
}
__device__ __forceinline__ uint32_t h2u(float lo, float hi) {
    __half2 h = __floats2half2_rn(lo, hi);
    return *(uint32_t*)&h;
}
__device__ __forceinline__ uint32_t smem_u32(const void* p) {
    return (uint32_t)__cvta_generic_to_shared(p);
}
__device__ __forceinline__ void ldsm_x4(uint32_t& r0, uint32_t& r1, uint32_t& r2, uint32_t& r3,
                                        uint32_t addr) {
    asm volatile("ldmatrix.sync.aligned.m8n8.x4.shared.b16 {%0,%1,%2,%3}, [%4];"
                 : "=r"(r0), "=r"(r1), "=r"(r2), "=r"(r3) : "r"(addr));
}
__device__ __forceinline__ void cpa16(uint32_t dst, const void* src) {
    asm volatile("cp.async.ca.shared.global [%0], [%1], 16;" :: "r"(dst), "l"(src));
}
__device__ __forceinline__ void cpa_commit() {
    asm volatile("cp.async.commit_group;" ::: "memory");
}
__device__ __forceinline__ void cpa_wait2() {
    asm volatile("cp.async.wait_group 2;" ::: "memory");
}
__device__ __forceinline__ void cpa_wait0() {
    asm volatile("cp.async.wait_all;" ::: "memory");
}

#define AST2 132
#define BST2 20
#define BBUF (128 * BST2)
#define KV_SMEM ((128 * AST2 + 4 * BBUF) * 4)
#define FIN_SMEM ((32 * AST2 + 4 * BBUF) * 4)

// ======== prep: zero flags/idx/count + weights fp32->fp16 (fused) ========
__global__ void __launch_bounds__(256) prep(
    const float* __restrict__ Wk, const float* __restrict__ Wv,
    const float* __restrict__ Wq, const float* __restrict__ Wf)
{
    const int i = blockIdx.x * 256 + threadIdx.x;    // grid 512 -> 131072
    g_idx[i] = 0;
    if (i < NTOT / 4) ((int*)g_flag)[i] = 0;
    if (i == 0) g_count = 0;
    if (i < HID * HID) {
        g_Wk16[i] = __float2half_rn(Wk[i]);
        g_Wv16[i] = __float2half_rn(Wv[i]);
        g_Wq16[i] = __float2half_rn(Wq[i]);
        g_Wf16[i] = __float2half_rn(Wf[i]);
    }
}

__global__ void __launch_bounds__(256) mark(const int* __restrict__ st,
                                            const int* __restrict__ en) {
    const int w = (blockIdx.x * 256 + threadIdx.x) >> 5;   // grid 128 -> 1024 warps
    const int lane = threadIdx.x & 31;
#pragma unroll
    for (int q = 0; q < 4; q++) {
        const int s = w * 4 + q;
        const int a = st[s], b = en[s];
        for (int r = a + lane; r < b; r += 32) g_flag[r] = 1;
    }
}

__global__ void __launch_bounds__(256) compact() {
    const int i = blockIdx.x * 256 + threadIdx.x;
    const int lane = threadIdx.x & 31;
    const int f = g_flag[i];
    const unsigned mask = __ballot_sync(0xffffffffu, f);
    int base = 0;
    if (lane == 0 && mask) base = atomicAdd(&g_count, __popc(mask));
    base = __shfl_sync(0xffffffffu, base, 0);
    if (f) g_idx[base + __popc(mask & ((1u << lane) - 1u))] = i;
}

// issue one B chunk (128 n-rows x 32 k, fp16) via cp.async into ring slot
__device__ __forceinline__ void issue_b(const __half* W16, int nh, int kc,
                                        uint32_t bufb32, int tid) {
#pragma unroll
    for (int r = 0; r < 2; r++) {
        const int task = tid + r * 256;
        const int n = task >> 2;
        const int s = task & 3;
        cpa16(bufb32 + (uint32_t)((n * BST2 + s * 4) * 4),
              W16 + (size_t)(nh * 128 + n) * HID + kc * 32 + s * 8);
    }
}

// ============ fused K+V+Q projections: gather-GEMM over covered rows ============
__global__ void __launch_bounds__(256, 2)
kvq_mma(const float* __restrict__ soc, const float* __restrict__ enc,
        const float* __restrict__ bk, const float* __restrict__ bv,
        const float* __restrict__ bq,
        __half* __restrict__ Kout, __half* __restrict__ Vout,
        __half* __restrict__ Qout)
{
    extern __shared__ uint32_t sm32[];
    uint32_t* As = sm32;
    const uint32_t Abase = smem_u32(As);
    const uint32_t Bbase = Abase + 128 * AST2 * 4;

    const int tid = threadIdx.x;
    const int lane = tid & 31;
    const int wid = tid >> 5;
    const int wm = wid & 1;
    const int wn = wid >> 1;
    const int bm = blockIdx.x;
    const bool isQ = (bm >= NTOT / 128);
    const int rowblk = isQ ? (bm - NTOT / 128) : bm;
    const int ntc_total = isQ ? 16 : 32;
    const int gbase = rowblk * 128;

    if (!isQ && gbase >= g_count) return;

    const int arow = wm * 64 + (lane & 15);
    const int acol = (lane >> 4) << 2;
    const int brow = wn * 32 + ((lane >> 4) << 3) + (lane & 7);
    const int bcol = ((lane >> 3) & 1) << 2;

    const __half* WK16 = isQ ? g_Wq16 : g_Wk16;
    const __half* WV16 = isQ ? g_Wq16 : g_Wv16;
    issue_b(WK16, 0, 0, Bbase, tid);
    cpa_commit();
    issue_b(WK16, 0, 1, Bbase + BBUF * 4, tid);
    cpa_commit();

    // ---- stage A tile 128x256 -> fp16 (gathered rows for KV mode) ----
#pragma unroll
    for (int i = 0; i < 32; i++) {
        int idx = i * 256 + tid;
        int r = idx >> 6, c4 = (idx & 63) << 2;
        const size_t grow = isQ ? (size_t)(gbase + r) : (size_t)g_idx[gbase + r];
        const float* src = (isQ ? enc : soc) + grow * HID + c4;
        float4 v = *(const float4*)src;
        uint2 h;
        h.x = h2u(v.x, v.y);
        h.y = h2u(v.z, v.w);
        *(uint2*)&As[r * AST2 + (c4 >> 1)] = h;
    }
    __syncthreads();

    float acc[4][4][4];
#pragma unroll
    for (int i = 0; i < 4; i++)
#pragma unroll
        for (int j = 0; j < 4; j++)
#pragma unroll
            for (int t = 0; t < 4; t++) acc[i][j][t] = 0.0f;

    for (int tc = 0; tc < ntc_total; tc++) {
        const int p = tc >> 3;
        const int kc = tc & 7;

        uint32_t a0[4][4];
        {
            const int kb = kc * 16;
#pragma unroll
            for (int i = 0; i < 4; i++)
                ldsm_x4(a0[i][0], a0[i][1], a0[i][2], a0[i][3],
                        Abase + (uint32_t)(((arow + i * 16) * AST2 + kb + acol) * 4));
        }

        if (tc + 2 < ntc_total) {
            const int ntc = tc + 2;
            const int np = ntc >> 3, nkc = ntc & 7;
            const __half* W = (np < 2) ? WK16 : WV16;
            issue_b(W, np & 1, nkc, Bbase + (uint32_t)(((ntc) & 3) * BBUF * 4), tid);
        }
        cpa_commit();
        cpa_wait2();
        __syncthreads();

        const uint32_t Bb32 = Bbase + (uint32_t)((tc & 3) * BBUF * 4);

        // ks = 0
        {
            uint32_t b[4][2];
            ldsm_x4(b[0][0], b[0][1], b[1][0], b[1][1],
                    Bb32 + (uint32_t)((brow * BST2 + bcol) * 4));
            ldsm_x4(b[2][0], b[2][1], b[3][0], b[3][1],
                    Bb32 + (uint32_t)(((brow + 16) * BST2 + bcol) * 4));
#pragma unroll
            for (int i = 0; i < 4; i++)
#pragma unroll
                for (int j = 0; j < 4; j++) mma_f16(acc[i][j], a0[i], b[j]);
        }
        // ks = 1
        {
            const int kb = kc * 16 + 8;
            uint32_t a[4][4];
#pragma unroll
            for (int i = 0; i < 4; i++)
                ldsm_x4(a[i][0], a[i][1], a[i][2], a[i][3],
                        Abase + (uint32_t)(((arow + i * 16) * AST2 + kb + acol) * 4));
            uint32_t b[4][2];
            const int bk0 = 8 + bcol;
            ldsm_x4(b[0][0], b[0][1], b[1][0], b[1][1],
                    Bb32 + (uint32_t)((brow * BST2 + bk0) * 4));
            ldsm_x4(b[2][0], b[2][1], b[3][0], b[3][1],
                    Bb32 + (uint32_t)(((brow + 16) * BST2 + bk0) * 4));
#pragma unroll
            for (int i = 0; i < 4; i++)
#pragma unroll
                for (int j = 0; j < 4; j++) mma_f16(acc[i][j], a[i], b[j]);
        }

        if (kc == 7) {
            const int nh = p & 1;
            const int colw = nh * 128 + wn * 32 + (lane & 3) * 2;
            const int lrow = wm * 64 + (lane >> 2);
            if (isQ) {
#pragma unroll
                for (int j = 0; j < 4; j++) {
                    const float2 bb = *(const float2*)&bq[colw + j * 8];
#pragma unroll
                    for (int i = 0; i < 4; i++) {
                        const size_t r0 = (size_t)gbase + lrow + i * 16;
                        uint32_t u0 = h2u(fmaxf(acc[i][j][0] + bb.x, 0.0f) * 0.0625f,
                                          fmaxf(acc[i][j][1] + bb.y, 0.0f) * 0.0625f);
                        uint32_t u1 = h2u(fmaxf(acc[i][j][2] + bb.x, 0.0f) * 0.0625f,
                                          fmaxf(acc[i][j][3] + bb.y, 0.0f) * 0.0625f);
                        *(uint32_t*)&Qout[r0 * HID + colw + j * 8] = u0;
                        *(uint32_t*)&Qout[(r0 + 8) * HID + colw + j * 8] = u1;
#pragma unroll
                        for (int t = 0; t < 4; t++) acc[i][j][t] = 0.0f;
                    }
                }
            } else {
                const float* bias = (p < 2) ? bk : bv;
                __half* Cout = (p < 2) ? Kout : Vout;
#pragma unroll
                for (int i = 0; i < 4; i++) {
                    const size_t r0 = (size_t)g_idx[gbase + lrow + i * 16];
                    const size_t r1 = (size_t)g_idx[gbase + lrow + i * 16 + 8];
#pragma unroll
                    for (int j = 0; j < 4; j++) {
                        const float2 bb = *(const float2*)&bias[colw + j * 8];
                        uint32_t u0 = h2u(fmaxf(acc[i][j][0] + bb.x, 0.0f),
                                          fmaxf(acc[i][j][1] + bb.y, 0.0f));
                        uint32_t u1 = h2u(fmaxf(acc[i][j][2] + bb.x, 0.0f),
                                          fmaxf(acc[i][j][3] + bb.y, 0.0f));
                        *(uint32_t*)&Cout[r0 * HID + colw + j * 8] = u0;
                        *(uint32_t*)&Cout[r1 * HID + colw + j * 8] = u1;
#pragma unroll
                        for (int t = 0; t < 4; t++) acc[i][j][t] = 0.0f;
                    }
                }
            }
        }
    }
}

// ============ final projection: 32-row tiles, 128 CTAs (mma.sync fp16) ============
__global__ void __launch_bounds__(256, 2)
fin_mma(const __half* __restrict__ O, const float* __restrict__ bf,
        float* __restrict__ out)
{
    extern __shared__ uint32_t sm32[];
    uint32_t* As = sm32;
    const uint32_t Abase = smem_u32(As);
    const uint32_t Bbase = Abase + 32 * AST2 * 4;

    const int tid = threadIdx.x;
    const int lane = tid & 31;
    const int wid = tid >> 5;
    const int wm = wid & 1;
    const int wn = wid >> 1;
    const int bm = blockIdx.x;

    const int arow = wm * 16 + (lane & 15);
    const int acol = (lane >> 4) << 2;
    const int brow = wn * 32 + ((lane >> 4) << 3) + (lane & 7);
    const int bcol = ((lane >> 3) & 1) << 2;

    issue_b(g_Wf16, 0, 0, Bbase, tid);
    cpa_commit();
    issue_b(g_Wf16, 0, 1, Bbase + BBUF * 4, tid);
    cpa_commit();

    const __half* Ab = O + (size_t)bm * 32 * HID;
#pragma unroll
    for (int i = 0; i < 4; i++) {
        int idx = i * 256 + tid;
        int r = idx >> 5, c2 = (idx & 31) * 4;
        uint4 v = *(const uint4*)(Ab + (size_t)r * HID + c2 * 2);
        *(uint4*)&As[r * AST2 + c2] = v;
    }
    __syncthreads();

    float acc[4][4];
#pragma unroll
    for (int j = 0; j < 4; j++)
#pragma unroll
        for (int t = 0; t < 4; t++) acc[j][t] = 0.0f;

    for (int tc = 0; tc < 16; tc++) {
        const int p = tc >> 3;
        const int kc = tc & 7;

        uint32_t a0[4];
        ldsm_x4(a0[0], a0[1], a0[2], a0[3],
                Abase + (uint32_t)((arow * AST2 + kc * 16 + acol) * 4));

        if (tc + 2 < 16) {
            const int ntc = tc + 2;
            issue_b(g_Wf16, (ntc >> 3) & 1, ntc & 7,
                    Bbase + (uint32_t)((ntc & 3) * BBUF * 4), tid);
        }
        cpa_commit();
        cpa_wait2();
        __syncthreads();

        const uint32_t Bb32 = Bbase + (uint32_t)((tc & 3) * BBUF * 4);
        {
            uint32_t b[4][2];
            ldsm_x4(b[0][0], b[0][1], b[1][0], b[1][1],
                    Bb32 + (uint32_t)((brow * BST2 + bcol) * 4));
            ldsm_x4(b[2][0], b[2][1], b[3][0], b[3][1],
                    Bb32 + (uint32_t)(((brow + 16) * BST2 + bcol) * 4));
#pragma unroll
            for (int j = 0; j < 4; j++) mma_f16(acc[j], a0, b[j]);
        }
        {
            uint32_t a[4];
            ldsm_x4(a[0], a[1], a[2], a[3],
                    Abase + (uint32_t)((arow * AST2 + kc * 16 + 8 + acol) * 4));
            uint32_t b[4][2];
            const int bk0 = 8 + bcol;
            ldsm_x4(b[0][0], b[0][1], b[1][0], b[1][1],
                    Bb32 + (uint32_t)((brow * BST2 + bk0) * 4));
            ldsm_x4(b[2][0], b[2][1], b[3][0], b[3][1],
                    Bb32 + (uint32_t)(((brow + 16) * BST2 + bk0) * 4));
#pragma unroll
            for (int j = 0; j < 4; j++) mma_f16(acc[j], a, b[j]);
        }

        if (kc == 7) {
            const int nh = p & 1;
            const int colw = nh * 128 + wn * 32 + (lane & 3) * 2;
            const size_t rowb = (size_t)bm * 32 + wm * 16 + (lane >> 2);
#pragma unroll
            for (int j = 0; j < 4; j++) {
                const float2 bb = *(const float2*)&bf[colw + j * 8];
                float2 o0, o1;
                o0.x = acc[j][0] + bb.x;
                o0.y = acc[j][1] + bb.y;
                o1.x = acc[j][2] + bb.x;
                o1.y = acc[j][3] + bb.y;
                *(float2*)&out[rowb * HID + colw + j * 8] = o0;
                *(float2*)&out[(rowb + 8) * HID + colw + j * 8] = o1;
#pragma unroll
                for (int t = 0; t < 4; t++) acc[j][t] = 0.0f;
            }
        }
    }
}

// ===== attention: 1 CTA / sample; V prefetched to smem, K direct, fp16 Q =====
__global__ __launch_bounds__(256) void attn4(
    const __half* __restrict__ Q, const __half* __restrict__ K,
    const __half* __restrict__ V, const int* __restrict__ starts,
    const int* __restrict__ ends, __half* __restrict__ O)
{
    __shared__ __half Vs[64 * HID];    // 32 KB
    __shared__ float qs[256];
    __shared__ float sc[256];

    const int tid = threadIdx.x;
    const int lane = tid & 31;
    const int wid = tid >> 5;
    const int b = blockIdx.x;
    const int st = starts[b];
    const int len = ends[b] - st;      // 1..64

    // ---- issue V segment prefetch (len rows x 512 B) ----
    {
        const uint32_t vb = smem_u32(Vs);
        const int nch = len * 32;       // 16B chunks
        for (int c = tid; c < nch; c += 256)
            cpa16(vb + (uint32_t)c * 16, (const char*)(V + (size_t)st * HID) + (size_t)c * 16);
        cpa_commit();
    }

    qs[tid] = __half2float(Q[(size_t)b * HID + tid]);
    sc[tid] = -1e30f;
    __syncthreads();

    float4 q0 = *(const float4*)&qs[lane * 8];
    float4 q1 = *(const float4*)&qs[lane * 8 + 4];
    const int head = lane >> 3;

    // scores (K from gmem, overlaps with V prefetch)
#pragma unroll
    for (int rr = 0; rr < 8; rr++) {
        const int m = rr * 8 + wid;
        if (m < len) {
            uint4 raw = *(const uint4*)(K + (size_t)(st + m) * HID + lane * 8);
            float2 f0 = __half22float2(*(__half2*)&raw.x);
            float2 f1 = __half22float2(*(__half2*)&raw.y);
            float2 f2 = __half22float2(*(__half2*)&raw.z);
            float2 f3 = __half22float2(*(__half2*)&raw.w);
            float p = q0.x * f0.x + q0.y * f0.y + q0.z * f1.x + q0.w * f1.y
                    + q1.x * f2.x + q1.y * f2.y + q1.z * f3.x + q1.w * f3.y;
            p += __shfl_down_sync(0xffffffffu, p, 4);
            p += __shfl_down_sync(0xffffffffu, p, 2);
            p += __shfl_down_sync(0xffffffffu, p, 1);
            if ((lane & 7) == 0) sc[head * 64 + m] = p;
        }
    }
    __syncthreads();

    // softmax
    if (tid < 128) {
        const int h = tid >> 5, l = tid & 31;
        float v0 = sc[h * 64 + l];
        float v1 = sc[h * 64 + 32 + l];
        float mx = fmaxf(v0, v1);
#pragma unroll
        for (int off = 16; off > 0; off >>= 1)
            mx = fmaxf(mx, __shfl_xor_sync(0xffffffffu, mx, off));
        float e0 = __expf(v0 - mx);
        float e1 = __expf(v1 - mx);
        float sum = e0 + e1;
#pragma unroll
        for (int off = 16; off > 0; off >>= 1)
            sum += __shfl_xor_sync(0xffffffffu, sum, off);
        float inv = 1.0f / sum;
        sc[h * 64 + l] = e0 * inv;
        sc[h * 64 + 32 + l] = e1 * inv;
    }
    cpa_wait0();
    __syncthreads();

    // out: thread = output channel, V from smem
    {
        const int h = tid >> 6;
        const __half* vp = Vs + tid;
        const float* ap = &sc[h * 64];
        float o = 0.0f;
        int m = 0;
        for (; m + 4 <= len; m += 4) {
            float a0 = ap[m], a1 = ap[m + 1], a2 = ap[m + 2], a3 = ap[m + 3];
            float v0 = __half2float(vp[(m) * HID]);
            float v1 = __half2float(vp[(m + 1) * HID]);
            float v2 = __half2float(vp[(m + 2) * HID]);
            float v3 = __half2float(vp[(m + 3) * HID]);
            o = fmaf(a0, v0, o); o = fmaf(a1, v1, o);
            o = fmaf(a2, v2, o); o = fmaf(a3, v3, o);
        }
        for (; m < len; m++) o = fmaf(ap[m], __half2float(vp[m * HID]), o);
        O[(size_t)b * HID + tid] = __float2half(o);
    }
}

// ======================= launch =======================
extern "C" void kernel_launch(void* const* d_in, const int* in_sizes, int n_in,
                              void* d_out, int out_size)
{
    const float* enc = (const float*)d_in[0];
    const float* soc = (const float*)d_in[1];
    const float* Wq = (const float*)d_in[2];
    const float* bq = (const float*)d_in[3];
    const float* Wk = (const float*)d_in[4];
    const float* bk = (const float*)d_in[5];
    const float* Wv = (const float*)d_in[6];
    const float* bv = (const float*)d_in[7];
    const float* Wf = (const float*)d_in[8];
    const float* bf = (const float*)d_in[9];
    const int* st = (const int*)d_in[10];
    const int* en = (const int*)d_in[11];
    float* out = (float*)d_out;

    __half *qp, *kp, *vp, *op;
    cudaGetSymbolAddress((void**)&qp, g_Q);
    cudaGetSymbolAddress((void**)&kp, g_K);
    cudaGetSymbolAddress((void**)&vp, g_V);
    cudaGetSymbolAddress((void**)&op, g_O);

    cudaFuncSetAttribute(kvq_mma, cudaFuncAttributeMaxDynamicSharedMemorySize, KV_SMEM);
    cudaFuncSetAttribute(fin_mma, cudaFuncAttributeMaxDynamicSharedMemorySize, FIN_SMEM);

    // prep: zero coverage state + convert weights (fused)
    prep<<<NTOT / 256, 256>>>(Wk, Wv, Wq, Wf);
    // coverage: mark (plain stores) then compact (ballot scan)
    mark<<<128, 256>>>(st, en);
    compact<<<NTOT / 256, 256>>>();
    // fused K,V,Q projections (KV gathered over covered rows, fp16 outputs)
    kvq_mma<<<NTOT / 128 + NB / 128, 256, KV_SMEM>>>(
        soc, enc, bk, bv, bq, kp, vp, qp);
    // attention (V prefetched to smem, K direct, fp16 Q)
    attn4<<<NB, 256>>>(qp, kp, vp, st, en, op);
    // final projection via fp16 mma (32-row tiles)
    fin_mma<<<NB / 32, 256, FIN_SMEM>>>(op, bf, out);
}

// round 17
// speedup vs baseline: 1.0430x; 1.0172x over previous
#include <cuda_runtime.h>
#include <cuda_fp16.h>
#include <cstdint>

#define HID 256
#define NB 4096
#define NTOT 131072

// Scratch (allocation-free rule: __device__ globals).
// Coverage state is self-cleaning across calls: compact zeroes g_flag after
// reading, fin_mma resets g_count, and kvq clamps idx reads so g_idx needs no
// zero-fill. Statics start zero-initialized, so the invariant holds on call 1.
__device__ __half g_Q[(size_t)NB * HID];
__device__ __half g_K[(size_t)NTOT * HID];
__device__ __half g_V[(size_t)NTOT * HID];
__device__ __half g_O[(size_t)NB * HID];
__device__ __half g_Wk16[HID * HID];
__device__ __half g_Wv16[HID * HID];
__device__ __half g_Wq16[HID * HID];
__device__ __half g_Wf16[HID * HID];
__device__ int    g_idx[NTOT];
__device__ unsigned char g_flag[NTOT];
__device__ int    g_count;

// ======================= helpers =======================
__device__ __forceinline__ void mma_f16(float* d, const uint32_t* a, const uint32_t* b) {
    asm volatile(
        "mma.sync.aligned.m16n8k16.row.col.f32.f16.f16.f32 "
        "{%0,%1,%2,%3},{%4,%5,%6,%7},{%8,%9},{%0,%1,%2,%3};"
        : "+f"(d[0]), "+f"(d[1]), "+f"(d[2]), "+f"(d[3])
        : "r"(a[0]), "r"(a[1]), "r"(a[2]), "r"(a[3]), "r"(b[0]), "r"(b[1]));
}
__device__ __forceinline__ uint32_t h2u(float lo, float hi) {
    __half2 h = __floats2half2_rn(lo, hi);
    return *(uint32_t*)&h;
}
__device__ __forceinline__ uint32_t smem_u32(const void* p) {
    return (uint32_t)__cvta_generic_to_shared(p);
}
__device__ __forceinline__ void ldsm_x4(uint32_t& r0, uint32_t& r1, uint32_t& r2, uint32_t& r3,
                                        uint32_t addr) {
    asm volatile("ldmatrix.sync.aligned.m8n8.x4.shared.b16 {%0,%1,%2,%3}, [%4];"
                 : "=r"(r0), "=r"(r1), "=r"(r2), "=r"(r3) : "r"(addr));
}
__device__ __forceinline__ void cpa16(uint32_t dst, const void* src) {
    asm volatile("cp.async.ca.shared.global [%0], [%1], 16;" :: "r"(dst), "l"(src));
}
__device__ __forceinline__ void cpa_commit() {
    asm volatile("cp.async.commit_group;" ::: "memory");
}
__device__ __forceinline__ void cpa_wait2() {
    asm volatile("cp.async.wait_group 2;" ::: "memory");
}
__device__ __forceinline__ void cpa_wait0() {
    asm volatile("cp.async.wait_all;" ::: "memory");
}

#define AST2 132
#define BST2 20
#define BBUF (128 * BST2)
#define KV_SMEM ((128 * AST2 + 4 * BBUF) * 4)
#define FIN_SMEM ((32 * AST2 + 4 * BBUF) * 4)

// ======== prep: weights fp32->fp16 (blocks 0..255) + mark coverage (256..383) ========
__global__ void __launch_bounds__(256) prep2(
    const float* __restrict__ Wk, const float* __restrict__ Wv,
    const float* __restrict__ Wq, const float* __restrict__ Wf,
    const int* __restrict__ st, const int* __restrict__ en)
{
    const int blk = blockIdx.x;
    if (blk < 256) {
        const int i = blk * 256 + threadIdx.x;    // 0..65535
        g_Wk16[i] = __float2half_rn(Wk[i]);
        g_Wv16[i] = __float2half_rn(Wv[i]);
        g_Wq16[i] = __float2half_rn(Wq[i]);
        g_Wf16[i] = __float2half_rn(Wf[i]);
    } else {
        // mark: flags guaranteed zero (compact cleared them last call)
        const int w = ((blk - 256) * 256 + threadIdx.x) >> 5;   // 0..1023
        const int lane = threadIdx.x & 31;
#pragma unroll
        for (int q = 0; q < 4; q++) {
            const int s = w * 4 + q;
            const int a = st[s], b = en[s];
            for (int r = a + lane; r < b; r += 32) g_flag[r] = 1;
        }
    }
}

// compact: ballot scan append, then clear flags for the next call
__global__ void __launch_bounds__(256) compact() {
    const int i = blockIdx.x * 256 + threadIdx.x;
    const int lane = threadIdx.x & 31;
    const int f = g_flag[i];
    const unsigned mask = __ballot_sync(0xffffffffu, f);
    int base = 0;
    if (lane == 0 && mask) base = atomicAdd(&g_count, __popc(mask));
    base = __shfl_sync(0xffffffffu, base, 0);
    if (f) {
        g_idx[base + __popc(mask & ((1u << lane) - 1u))] = i;
        g_flag[i] = 0;
    }
}

// issue one B chunk (128 n-rows x 32 k, fp16) via cp.async into ring slot
__device__ __forceinline__ void issue_b(const __half* W16, int nh, int kc,
                                        uint32_t bufb32, int tid) {
#pragma unroll
    for (int r = 0; r < 2; r++) {
        const int task = tid + r * 256;
        const int n = task >> 2;
        const int s = task & 3;
        cpa16(bufb32 + (uint32_t)((n * BST2 + s * 4) * 4),
              W16 + (size_t)(nh * 128 + n) * HID + kc * 32 + s * 8);
    }
}

// ============ fused K+V+Q projections: gather-GEMM over covered rows ============
__global__ void __launch_bounds__(256, 2)
kvq_mma(const float* __restrict__ soc, const float* __restrict__ enc,
        const float* __restrict__ bk, const float* __restrict__ bv,
        const float* __restrict__ bq,
        __half* __restrict__ Kout, __half* __restrict__ Vout,
        __half* __restrict__ Qout)
{
    extern __shared__ uint32_t sm32[];
    uint32_t* As = sm32;
    const uint32_t Abase = smem_u32(As);
    const uint32_t Bbase = Abase + 128 * AST2 * 4;

    const int tid = threadIdx.x;
    const int lane = tid & 31;
    const int wid = tid >> 5;
    const int wm = wid & 1;
    const int wn = wid >> 1;
    const int bm = blockIdx.x;
    const bool isQ = (bm >= NTOT / 128);
    const int rowblk = isQ ? (bm - NTOT / 128) : bm;
    const int ntc_total = isQ ? 16 : 32;
    const int gbase = rowblk * 128;
    const int cnt = g_count;

    if (!isQ && gbase >= cnt) return;
    const int cmax = cnt - 1;    // clamp bound for idx reads (tail padding)

    const int arow = wm * 64 + (lane & 15);
    const int acol = (lane >> 4) << 2;
    const int brow = wn * 32 + ((lane >> 4) << 3) + (lane & 7);
    const int bcol = ((lane >> 3) & 1) << 2;

    const __half* WK16 = isQ ? g_Wq16 : g_Wk16;
    const __half* WV16 = isQ ? g_Wq16 : g_Wv16;
    issue_b(WK16, 0, 0, Bbase, tid);
    cpa_commit();
    issue_b(WK16, 0, 1, Bbase + BBUF * 4, tid);
    cpa_commit();

    // ---- stage A tile 128x256 -> fp16 (gathered rows for KV mode, clamped) ----
#pragma unroll
    for (int i = 0; i < 32; i++) {
        int idx = i * 256 + tid;
        int r = idx >> 6, c4 = (idx & 63) << 2;
        const size_t grow = isQ ? (size_t)(gbase + r)
                                : (size_t)g_idx[min(gbase + r, cmax)];
        const float* src = (isQ ? enc : soc) + grow * HID + c4;
        float4 v = *(const float4*)src;
        uint2 h;
        h.x = h2u(v.x, v.y);
        h.y = h2u(v.z, v.w);
        *(uint2*)&As[r * AST2 + (c4 >> 1)] = h;
    }
    __syncthreads();

    float acc[4][4][4];
#pragma unroll
    for (int i = 0; i < 4; i++)
#pragma unroll
        for (int j = 0; j < 4; j++)
#pragma unroll
            for (int t = 0; t < 4; t++) acc[i][j][t] = 0.0f;

    for (int tc = 0; tc < ntc_total; tc++) {
        const int p = tc >> 3;
        const int kc = tc & 7;

        uint32_t a0[4][4];
        {
            const int kb = kc * 16;
#pragma unroll
            for (int i = 0; i < 4; i++)
                ldsm_x4(a0[i][0], a0[i][1], a0[i][2], a0[i][3],
                        Abase + (uint32_t)(((arow + i * 16) * AST2 + kb + acol) * 4));
        }

        if (tc + 2 < ntc_total) {
            const int ntc = tc + 2;
            const int np = ntc >> 3, nkc = ntc & 7;
            const __half* W = (np < 2) ? WK16 : WV16;
            issue_b(W, np & 1, nkc, Bbase + (uint32_t)(((ntc) & 3) * BBUF * 4), tid);
        }
        cpa_commit();
        cpa_wait2();
        __syncthreads();

        const uint32_t Bb32 = Bbase + (uint32_t)((tc & 3) * BBUF * 4);

        // ks = 0
        {
            uint32_t b[4][2];
            ldsm_x4(b[0][0], b[0][1], b[1][0], b[1][1],
                    Bb32 + (uint32_t)((brow * BST2 + bcol) * 4));
            ldsm_x4(b[2][0], b[2][1], b[3][0], b[3][1],
                    Bb32 + (uint32_t)(((brow + 16) * BST2 + bcol) * 4));
#pragma unroll
            for (int i = 0; i < 4; i++)
#pragma unroll
                for (int j = 0; j < 4; j++) mma_f16(acc[i][j], a0[i], b[j]);
        }
        // ks = 1
        {
            const int kb = kc * 16 + 8;
            uint32_t a[4][4];
#pragma unroll
            for (int i = 0; i < 4; i++)
                ldsm_x4(a[i][0], a[i][1], a[i][2], a[i][3],
                        Abase + (uint32_t)(((arow + i * 16) * AST2 + kb + acol) * 4));
            uint32_t b[4][2];
            const int bk0 = 8 + bcol;
            ldsm_x4(b[0][0], b[0][1], b[1][0], b[1][1],
                    Bb32 + (uint32_t)((brow * BST2 + bk0) * 4));
            ldsm_x4(b[2][0], b[2][1], b[3][0], b[3][1],
                    Bb32 + (uint32_t)(((brow + 16) * BST2 + bk0) * 4));
#pragma unroll
            for (int i = 0; i < 4; i++)
#pragma unroll
                for (int j = 0; j < 4; j++) mma_f16(acc[i][j], a[i], b[j]);
        }

        if (kc == 7) {
            const int nh = p & 1;
            const int colw = nh * 128 + wn * 32 + (lane & 3) * 2;
            const int lrow = wm * 64 + (lane >> 2);
            if (isQ) {
#pragma unroll
                for (int j = 0; j < 4; j++) {
                    const float2 bb = *(const float2*)&bq[colw + j * 8];
#pragma unroll
                    for (int i = 0; i < 4; i++) {
                        const size_t r0 = (size_t)gbase + lrow + i * 16;
                        uint32_t u0 = h2u(fmaxf(acc[i][j][0] + bb.x, 0.0f) * 0.0625f,
                                          fmaxf(acc[i][j][1] + bb.y, 0.0f) * 0.0625f);
                        uint32_t u1 = h2u(fmaxf(acc[i][j][2] + bb.x, 0.0f) * 0.0625f,
                                          fmaxf(acc[i][j][3] + bb.y, 0.0f) * 0.0625f);
                        *(uint32_t*)&Qout[r0 * HID + colw + j * 8] = u0;
                        *(uint32_t*)&Qout[(r0 + 8) * HID + colw + j * 8] = u1;
#pragma unroll
                        for (int t = 0; t < 4; t++) acc[i][j][t] = 0.0f;
                    }
                }
            } else {
                const float* bias = (p < 2) ? bk : bv;
                __half* Cout = (p < 2) ? Kout : Vout;
#pragma unroll
                for (int i = 0; i < 4; i++) {
                    const size_t r0 = (size_t)g_idx[min(gbase + lrow + i * 16, cmax)];
                    const size_t r1 = (size_t)g_idx[min(gbase + lrow + i * 16 + 8, cmax)];
#pragma unroll
                    for (int j = 0; j < 4; j++) {
                        const float2 bb = *(const float2*)&bias[colw + j * 8];
                        uint32_t u0 = h2u(fmaxf(acc[i][j][0] + bb.x, 0.0f),
                                          fmaxf(acc[i][j][1] + bb.y, 0.0f));
                        uint32_t u1 = h2u(fmaxf(acc[i][j][2] + bb.x, 0.0f),
                                          fmaxf(acc[i][j][3] + bb.y, 0.0f));
                        *(uint32_t*)&Cout[r0 * HID + colw + j * 8] = u0;
                        *(uint32_t*)&Cout[r1 * HID + colw + j * 8] = u1;
#pragma unroll
                        for (int t = 0; t < 4; t++) acc[i][j][t] = 0.0f;
                    }
                }
            }
        }
    }
}

// ============ final projection: 32-row tiles, 128 CTAs (mma.sync fp16) ============
__global__ void __launch_bounds__(256, 2)
fin_mma(const __half* __restrict__ O, const float* __restrict__ bf,
        float* __restrict__ out)
{
    extern __shared__ uint32_t sm32[];
    uint32_t* As = sm32;
    const uint32_t Abase = smem_u32(As);
    const uint32_t Bbase = Abase + 32 * AST2 * 4;

    const int tid = threadIdx.x;
    const int lane = tid & 31;
    const int wid = tid >> 5;
    const int wm = wid & 1;
    const int wn = wid >> 1;
    const int bm = blockIdx.x;

    // reset coverage counter for the next call (self-cleaning state)
    if (bm == 0 && tid == 0) g_count = 0;

    const int arow = wm * 16 + (lane & 15);
    const int acol = (lane >> 4) << 2;
    const int brow = wn * 32 + ((lane >> 4) << 3) + (lane & 7);
    const int bcol = ((lane >> 3) & 1) << 2;

    issue_b(g_Wf16, 0, 0, Bbase, tid);
    cpa_commit();
    issue_b(g_Wf16, 0, 1, Bbase + BBUF * 4, tid);
    cpa_commit();

    const __half* Ab = O + (size_t)bm * 32 * HID;
#pragma unroll
    for (int i = 0; i < 4; i++) {
        int idx = i * 256 + tid;
        int r = idx >> 5, c2 = (idx & 31) * 4;
        uint4 v = *(const uint4*)(Ab + (size_t)r * HID + c2 * 2);
        *(uint4*)&As[r * AST2 + c2] = v;
    }
    __syncthreads();

    float acc[4][4];
#pragma unroll
    for (int j = 0; j < 4; j++)
#pragma unroll
        for (int t = 0; t < 4; t++) acc[j][t] = 0.0f;

    for (int tc = 0; tc < 16; tc++) {
        const int p = tc >> 3;
        const int kc = tc & 7;

        uint32_t a0[4];
        ldsm_x4(a0[0], a0[1], a0[2], a0[3],
                Abase + (uint32_t)((arow * AST2 + kc * 16 + acol) * 4));

        if (tc + 2 < 16) {
            const int ntc = tc + 2;
            issue_b(g_Wf16, (ntc >> 3) & 1, ntc & 7,
                    Bbase + (uint32_t)((ntc & 3) * BBUF * 4), tid);
        }
        cpa_commit();
        cpa_wait2();
        __syncthreads();

        const uint32_t Bb32 = Bbase + (uint32_t)((tc & 3) * BBUF * 4);
        {
            uint32_t b[4][2];
            ldsm_x4(b[0][0], b[0][1], b[1][0], b[1][1],
                    Bb32 + (uint32_t)((brow * BST2 + bcol) * 4));
            ldsm_x4(b[2][0], b[2][1], b[3][0], b[3][1],
                    Bb32 + (uint32_t)(((brow + 16) * BST2 + bcol) * 4));
#pragma unroll
            for (int j = 0; j < 4; j++) mma_f16(acc[j], a0, b[j]);
        }
        {
            uint32_t a[4];
            ldsm_x4(a[0], a[1], a[2], a[3],
                    Abase + (uint32_t)((arow * AST2 + kc * 16 + 8 + acol) * 4));
            uint32_t b[4][2];
            const int bk0 = 8 + bcol;
            ldsm_x4(b[0][0], b[0][1], b[1][0], b[1][1],
                    Bb32 + (uint32_t)((brow * BST2 + bk0) * 4));
            ldsm_x4(b[2][0], b[2][1], b[3][0], b[3][1],
                    Bb32 + (uint32_t)(((brow + 16) * BST2 + bk0) * 4));
#pragma unroll
            for (int j = 0; j < 4; j++) mma_f16(acc[j], a, b[j]);
        }

        if (kc == 7) {
            const int nh = p & 1;
            const int colw = nh * 128 + wn * 32 + (lane & 3) * 2;
            const size_t rowb = (size_t)bm * 32 + wm * 16 + (lane >> 2);
#pragma unroll
            for (int j = 0; j < 4; j++) {
                const float2 bb = *(const float2*)&bf[colw + j * 8];
                float2 o0, o1;
                o0.x = acc[j][0] + bb.x;
                o0.y = acc[j][1] + bb.y;
                o1.x = acc[j][2] + bb.x;
                o1.y = acc[j][3] + bb.y;
                *(float2*)&out[rowb * HID + colw + j * 8] = o0;
                *(float2*)&out[(rowb + 8) * HID + colw + j * 8] = o1;
#pragma unroll
                for (int t = 0; t < 4; t++) acc[j][t] = 0.0f;
            }
        }
    }
}

// ===== attention: 1 CTA / sample; V prefetched to smem, K direct, fp16 Q =====
__global__ __launch_bounds__(256) void attn4(
    const __half* __restrict__ Q, const __half* __restrict__ K,
    const __half* __restrict__ V, const int* __restrict__ starts,
    const int* __restrict__ ends, __half* __restrict__ O)
{
    __shared__ __half Vs[64 * HID];    // 32 KB
    __shared__ float qs[256];
    __shared__ float sc[256];

    const int tid = threadIdx.x;
    const int lane = tid & 31;
    const int wid = tid >> 5;
    const int b = blockIdx.x;
    const int st = starts[b];
    const int len = ends[b] - st;      // 1..64

    // ---- issue V segment prefetch (len rows x 512 B) ----
    {
        const uint32_t vb = smem_u32(Vs);
        const int nch = len * 32;       // 16B chunks
        for (int c = tid; c < nch; c += 256)
            cpa16(vb + (uint32_t)c * 16, (const char*)(V + (size_t)st * HID) + (size_t)c * 16);
        cpa_commit();
    }

    qs[tid] = __half2float(Q[(size_t)b * HID + tid]);
    sc[tid] = -1e30f;
    __syncthreads();

    float4 q0 = *(const float4*)&qs[lane * 8];
    float4 q1 = *(const float4*)&qs[lane * 8 + 4];
    const int head = lane >> 3;

    // scores (K from gmem, overlaps with V prefetch)
#pragma unroll
    for (int rr = 0; rr < 8; rr++) {
        const int m = rr * 8 + wid;
        if (m < len) {
            uint4 raw = *(const uint4*)(K + (size_t)(st + m) * HID + lane * 8);
            float2 f0 = __half22float2(*(__half2*)&raw.x);
            float2 f1 = __half22float2(*(__half2*)&raw.y);
            float2 f2 = __half22float2(*(__half2*)&raw.z);
            float2 f3 = __half22float2(*(__half2*)&raw.w);
            float p = q0.x * f0.x + q0.y * f0.y + q0.z * f1.x + q0.w * f1.y
                    + q1.x * f2.x + q1.y * f2.y + q1.z * f3.x + q1.w * f3.y;
            p += __shfl_down_sync(0xffffffffu, p, 4);
            p += __shfl_down_sync(0xffffffffu, p, 2);
            p += __shfl_down_sync(0xffffffffu, p, 1);
            if ((lane & 7) == 0) sc[head * 64 + m] = p;
        }
    }
    __syncthreads();

    // softmax
    if (tid < 128) {
        const int h = tid >> 5, l = tid & 31;
        float v0 = sc[h * 64 + l];
        float v1 = sc[h * 64 + 32 + l];
        float mx = fmaxf(v0, v1);
#pragma unroll
        for (int off = 16; off > 0; off >>= 1)
            mx = fmaxf(mx, __shfl_xor_sync(0xffffffffu, mx, off));
        float e0 = __expf(v0 - mx);
        float e1 = __expf(v1 - mx);
        float sum = e0 + e1;
#pragma unroll
        for (int off = 16; off > 0; off >>= 1)
            sum += __shfl_xor_sync(0xffffffffu, sum, off);
        float inv = 1.0f / sum;
        sc[h * 64 + l] = e0 * inv;
        sc[h * 64 + 32 + l] = e1 * inv;
    }
    cpa_wait0();
    __syncthreads();

    // out: thread = output channel, V from smem
    {
        const int h = tid >> 6;
        const __half* vp = Vs + tid;
        const float* ap = &sc[h * 64];
        float o = 0.0f;
        int m = 0;
        for (; m + 4 <= len; m += 4) {
            float a0 = ap[m], a1 = ap[m + 1], a2 = ap[m + 2], a3 = ap[m + 3];
            float v0 = __half2float(vp[(m) * HID]);
            float v1 = __half2float(vp[(m + 1) * HID]);
            float v2 = __half2float(vp[(m + 2) * HID]);
            float v3 = __half2float(vp[(m + 3) * HID]);
            o = fmaf(a0, v0, o); o = fmaf(a1, v1, o);
            o = fmaf(a2, v2, o); o = fmaf(a3, v3, o);
        }
        for (; m < len; m++) o = fmaf(ap[m], __half2float(vp[m * HID]), o);
        O[(size_t)b * HID + tid] = __float2half(o);
    }
}

// ======================= launch =======================
extern "C" void kernel_launch(void* const* d_in, const int* in_sizes, int n_in,
                              void* d_out, int out_size)
{
    const float* enc = (const float*)d_in[0];
    const float* soc = (const float*)d_in[1];
    const float* Wq = (const float*)d_in[2];
    const float* bq = (const float*)d_in[3];
    const float* Wk = (const float*)d_in[4];
    const float* bk = (const float*)d_in[5];
    const float* Wv = (const float*)d_in[6];
    const float* bv = (const float*)d_in[7];
    const float* Wf = (const float*)d_in[8];
    const float* bf = (const float*)d_in[9];
    const int* st = (const int*)d_in[10];
    const int* en = (const int*)d_in[11];
    float* out = (float*)d_out;

    __half *qp, *kp, *vp, *op;
    cudaGetSymbolAddress((void**)&qp, g_Q);
    cudaGetSymbolAddress((void**)&kp, g_K);
    cudaGetSymbolAddress((void**)&vp, g_V);
    cudaGetSymbolAddress((void**)&op, g_O);

    cudaFuncSetAttribute(kvq_mma, cudaFuncAttributeMaxDynamicSharedMemorySize, KV_SMEM);
    cudaFuncSetAttribute(fin_mma, cudaFuncAttributeMaxDynamicSharedMemorySize, FIN_SMEM);

    // prep: weight conversion + coverage mark (flags pre-cleared by last call)
    prep2<<<384, 256>>>(Wk, Wv, Wq, Wf, st, en);
    // compact (ballot scan) + clear flags for next call
    compact<<<NTOT / 256, 256>>>();
    // fused K,V,Q projections (KV gathered over covered rows, fp16 outputs)
    kvq_mma<<<NTOT / 128 + NB / 128, 256, KV_SMEM>>>(
        soc, enc, bk, bv, bq, kp, vp, qp);
    // attention (V prefetched to smem, K direct, fp16 Q)
    attn4<<<NB, 256>>>(qp, kp, vp, st, en, op);
    // final projection via fp16 mma (32-row tiles) + g_count reset
    fin_mma<<<NB / 32, 256, FIN_SMEM>>>(op, bf, out);
}